// round 1
// baseline (speedup 1.0000x reference)
#include <cuda_runtime.h>
#include <math.h>

// RoIAlign_withBanks: N=2000 boxes, C=256 channels, G=7 pooled, 6 FPN levels
// dims = {38,19,10,5,3,1}. Output [N, C, G, G] fp32.
//
// Strategy: one block per box. Threads redundantly compute the FPN level
// (cheap, deterministic). First 49 threads precompute packed corner offsets +
// bilinear weights for all (i,j) grid cells into shared memory. Then all 256
// threads sweep the 12544 output elements of the box with a linear mapping
// idx = t + 256*it -> fully coalesced 128B/warp stores. Fmap reads hit L2
// (all fmaps total ~2MB) and largely L1 (per-box working set ~patch*256ch).

#define G_POOL 7
#define NCH 256
#define CELLS (G_POOL * G_POOL)          // 49
#define ELEMS (NCH * CELLS)              // 12544
#define TPB 256

__global__ __launch_bounds__(TPB) void roialign_banks_kernel(
    const float* __restrict__ boxes,
    const float* __restrict__ f0, const float* __restrict__ f1,
    const float* __restrict__ f2, const float* __restrict__ f3,
    const float* __restrict__ f4, const float* __restrict__ f5,
    float* __restrict__ out)
{
    const int n = blockIdx.x;
    const int t = threadIdx.x;

    // Box (broadcast load, all threads same address -> L1 broadcast)
    const float bx1 = boxes[4 * n + 0];
    const float by1 = boxes[4 * n + 1];
    const float bx2 = boxes[4 * n + 2];
    const float by2 = boxes[4 * n + 3];

    // Level selection: lvl = clip(floor(5 + log2(sqrt(w*h))), 0, 5)
    const float avg = sqrtf((bx2 - bx1) * (by2 - by1));
    const float lf  = floorf(5.0f + log2f(avg));
    const int lvl   = (int)fminf(fmaxf(lf, 0.0f), 5.0f);

    const float* fm;
    int D;
    switch (lvl) {
        case 0:  fm = f0; D = 38; break;
        case 1:  fm = f1; D = 19; break;
        case 2:  fm = f2; D = 10; break;
        case 3:  fm = f3; D = 5;  break;
        case 4:  fm = f4; D = 3;  break;
        default: fm = f5; D = 1;  break;
    }
    const int DD = D * D;

    // Per-cell precompute: corner offsets within a channel plane + weights.
    __shared__ int4   s_off[CELLS];   // {o00, o10, o01, o11}
    __shared__ float2 s_w[CELLS];     // {wx0, wy0}

    if (t < CELLS) {
        const int i = t / G_POOL;     // x-grid index (rows of fmap)
        const int j = t % G_POOL;     // y-grid index (cols of fmap)
        // xr = clip(x1 + i*(x2-x1)/6, 0, 1)  (mul then div, matching jnp)
        float xr = fminf(fmaxf(bx1 + (float)i * (bx2 - bx1) / 6.0f, 0.0f), 1.0f);
        float yr = fminf(fmaxf(by1 + (float)j * (by2 - by1) / 6.0f, 0.0f), 1.0f);
        float ux = xr * (float)(D - 1);
        float uy = yr * (float)(D - 1);
        float fx = floorf(ux);
        float fy = floorf(uy);
        int ix0 = (int)fx;
        int iy0 = (int)fy;
        int ix1 = (int)ceilf(ux);
        int iy1 = (int)ceilf(uy);
        // With ceil-floor in {0,1}, reference weights collapse to 1-frac.
        s_off[t] = make_int4(ix0 * D + iy0, ix1 * D + iy0,
                             ix0 * D + iy1, ix1 * D + iy1);
        s_w[t]   = make_float2(1.0f - (ux - fx), 1.0f - (uy - fy));
    }
    __syncthreads();

    float* __restrict__ outn = out + (size_t)n * ELEMS;

    // Linear mapping idx = t + 256*it over [0, 12544): coalesced stores.
    // Track (c, pos) incrementally: 256 = 5*49 + 11.
    int c   = t / CELLS;
    int pos = t - c * CELLS;

#pragma unroll 7
    for (int it = 0; it < ELEMS / TPB; ++it) {
        const int4   o = s_off[pos];
        const float2 w = s_w[pos];
        const float* f = fm + c * DD;
        const float wx1 = 1.0f - w.x;
        const float v0 = w.x * __ldg(f + o.x) + wx1 * __ldg(f + o.y);
        const float v1 = w.x * __ldg(f + o.z) + wx1 * __ldg(f + o.w);
        outn[c * CELLS + pos] = w.y * v0 + (1.0f - w.y) * v1;
        pos += 11;
        c   += 5;
        if (pos >= CELLS) { pos -= CELLS; ++c; }
    }
}

extern "C" void kernel_launch(void* const* d_in, const int* in_sizes, int n_in,
                              void* d_out, int out_size)
{
    const int N = in_sizes[0] / 4;
    roialign_banks_kernel<<<N, TPB>>>(
        (const float*)d_in[0],
        (const float*)d_in[1], (const float*)d_in[2], (const float*)d_in[3],
        (const float*)d_in[4], (const float*)d_in[5], (const float*)d_in[6],
        (float*)d_out);
}

// round 3
// speedup vs baseline: 1.0441x; 1.0441x over previous
#include <cuda_runtime.h>
#include <math.h>

// RoIAlign_withBanks: N=2000 boxes, C=256, G=7, 6 FPN levels, dims {38,19,10,5,3,1}.
// Output [N, C, 7, 7] fp32.
//
// Strategy (R2, re-benched after infra failure): one block per box, 224
// threads. 49 grid cells precomputed once into shared as {int4 corner
// offsets, float4 folded bilinear weights}. Each thread iterates linear index
// idx = t + 224*it over [0, 3136) (= 64 channels x 49 cells) and computes the
// SAME CELL for 4 channel groups {c, c+64, c+128, c+192}: one shared-load
// pair serves 4 output elements, weights pre-folded to 4 FFMAs per element,
// stores coalesced (consecutive threads -> consecutive idx) in 4 streams.

#define G_POOL 7
#define CELLS 49               // 7*7
#define QCH 64                 // channels per group (256/4)
#define QELEMS (QCH * CELLS)   // 3136
#define TPB 224                // 3136 / 224 = 14 iterations exactly
#define ITERS (QELEMS / TPB)   // 14

__global__ __launch_bounds__(TPB) void roialign_banks_kernel(
    const float* __restrict__ boxes,
    const float* __restrict__ f0, const float* __restrict__ f1,
    const float* __restrict__ f2, const float* __restrict__ f3,
    const float* __restrict__ f4, const float* __restrict__ f5,
    float* __restrict__ out)
{
    const int n = blockIdx.x;
    const int t = threadIdx.x;

    // Box (L1-broadcast loads)
    const float bx1 = boxes[4 * n + 0];
    const float by1 = boxes[4 * n + 1];
    const float bx2 = boxes[4 * n + 2];
    const float by2 = boxes[4 * n + 3];

    // Level: clip(floor(5 + log2(sqrt(w*h))), 0, 5)
    const float avg = sqrtf((bx2 - bx1) * (by2 - by1));
    const float lf  = floorf(5.0f + log2f(avg));
    const int lvl   = (int)fminf(fmaxf(lf, 0.0f), 5.0f);

    const float* fm;
    int D;
    switch (lvl) {
        case 0:  fm = f0; D = 38; break;
        case 1:  fm = f1; D = 19; break;
        case 2:  fm = f2; D = 10; break;
        case 3:  fm = f3; D = 5;  break;
        case 4:  fm = f4; D = 3;  break;
        default: fm = f5; D = 1;  break;
    }
    const int DD = D * D;

    __shared__ int4   s_off[CELLS];   // {o00, o10, o01, o11} offsets in plane
    __shared__ float4 s_w[CELLS];     // {w00, w10, w01, w11} folded weights

    if (t < CELLS) {
        const int i = t / G_POOL;     // x-grid index (fmap rows)
        const int j = t % G_POOL;     // y-grid index (fmap cols)
        float xr = fminf(fmaxf(bx1 + (float)i * (bx2 - bx1) / 6.0f, 0.0f), 1.0f);
        float yr = fminf(fmaxf(by1 + (float)j * (by2 - by1) / 6.0f, 0.0f), 1.0f);
        float ux = xr * (float)(D - 1);
        float uy = yr * (float)(D - 1);
        float fx = floorf(ux);
        float fy = floorf(uy);
        int ix0 = (int)fx;
        int iy0 = (int)fy;
        int ix1 = (int)ceilf(ux);
        int iy1 = (int)ceilf(uy);
        // ceil-floor is 0 or 1 -> reference weights collapse to (1-frac, frac)
        float px0 = 1.0f - (ux - fx);
        float py0 = 1.0f - (uy - fy);
        float px1 = 1.0f - px0;
        float py1 = 1.0f - py0;
        s_off[t] = make_int4(ix0 * D + iy0, ix1 * D + iy0,
                             ix0 * D + iy1, ix1 * D + iy1);
        s_w[t]   = make_float4(px0 * py0, px1 * py0, px0 * py1, px1 * py1);
    }
    __syncthreads();

    float* __restrict__ op = out + (size_t)n * (4 * QELEMS) + t;

    // idx = t + 224*it over [0, 3136). 224 = 4*49 + 28.
    int c   = t / CELLS;
    int pos = t - c * CELLS;
    const int strideCh = QCH * DD;    // 64 channel planes

    const float* p0 = fm + c * DD;
    const float* p1 = p0 + strideCh;
    const float* p2 = p0 + 2 * strideCh;
    const float* p3 = p0 + 3 * strideCh;

#pragma unroll 2
    for (int it = 0; it < ITERS; ++it) {
        const int4   o = s_off[pos];
        const float4 w = s_w[pos];

        float r0 = w.x * __ldg(p0 + o.x) + w.y * __ldg(p0 + o.y)
                 + w.z * __ldg(p0 + o.z) + w.w * __ldg(p0 + o.w);
        float r1 = w.x * __ldg(p1 + o.x) + w.y * __ldg(p1 + o.y)
                 + w.z * __ldg(p1 + o.z) + w.w * __ldg(p1 + o.w);
        float r2 = w.x * __ldg(p2 + o.x) + w.y * __ldg(p2 + o.y)
                 + w.z * __ldg(p2 + o.z) + w.w * __ldg(p2 + o.w);
        float r3 = w.x * __ldg(p3 + o.x) + w.y * __ldg(p3 + o.y)
                 + w.z * __ldg(p3 + o.z) + w.w * __ldg(p3 + o.w);

        op[0]          = r0;
        op[QELEMS]     = r1;
        op[2 * QELEMS] = r2;
        op[3 * QELEMS] = r3;

        // advance by TPB threads: c += 4, pos += 28, wrap once if needed
        pos += 28;
        int adv = 4 * DD;
        if (pos >= CELLS) { pos -= CELLS; adv += DD; }
        p0 += adv; p1 += adv; p2 += adv; p3 += adv;
        op += TPB;
    }
}

extern "C" void kernel_launch(void* const* d_in, const int* in_sizes, int n_in,
                              void* d_out, int out_size)
{
    const int N = in_sizes[0] / 4;
    roialign_banks_kernel<<<N, TPB>>>(
        (const float*)d_in[0],
        (const float*)d_in[1], (const float*)d_in[2], (const float*)d_in[3],
        (const float*)d_in[4], (const float*)d_in[5], (const float*)d_in[6],
        (float*)d_out);
}